// round 2
// baseline (speedup 1.0000x reference)
#include <cuda_runtime.h>

#define HH   128
#define NSEQ 256
#define BB   8
#define ROWS (BB * NSEQ)   // 2048

// scratch (allocation-free rule: __device__ globals)
__device__ float g_Ux[ROWS * HH];
__device__ float g_Vx[ROWS * HH];

// ---------------------------------------------------------------------------
// Kernel 1: Ux = (x @ U_w^T + U_b)*0.5 ; Vx = (x @ V_w^T + V_b)*0.5
// 256 blocks x 256 threads. Each block: 8 rows. W transposed in padded SMEM.
// ---------------------------------------------------------------------------
__global__ void uv_kernel(const float* __restrict__ x,
                          const float* __restrict__ Uw, const float* __restrict__ Ub,
                          const float* __restrict__ Vw, const float* __restrict__ Vb) {
    extern __shared__ float sm[];
    float* sWu = sm;                    // 128*129
    float* sWv = sm + 128 * 129;        // 128*129
    float* sx  = sm + 2 * 128 * 129;    // 8*128
    const int tid = threadIdx.x;

    // load W transposed: sW[h*129 + k] = W[k*128 + h]  (pad 129 -> conflict-free)
    for (int idx = tid; idx < HH * HH; idx += 256) {
        int k = idx >> 7, h = idx & 127;
        sWu[h * 129 + k] = Uw[idx];
        sWv[h * 129 + k] = Vw[idx];
    }
    const int r0 = blockIdx.x * 8;
    for (int idx = tid; idx < 8 * HH; idx += 256)
        sx[idx] = x[r0 * HH + idx];
    __syncthreads();

    const int mat = tid >> 7;      // 0 = U, 1 = V
    const int k   = tid & 127;
    const float* W = mat ? sWv : sWu;

    float acc[8];
#pragma unroll
    for (int r = 0; r < 8; r++) acc[r] = 0.0f;

#pragma unroll 8
    for (int h = 0; h < HH; h++) {
        float wv = W[h * 129 + k];
#pragma unroll
        for (int r = 0; r < 8; r++) acc[r] += sx[r * HH + h] * wv;
    }

    const float bias = mat ? Vb[k] : Ub[k];
    float* dst = mat ? g_Vx : g_Ux;
#pragma unroll
    for (int r = 0; r < 8; r++)
        dst[(r0 + r) * HH + k] = (acc[r] + bias) * 0.5f;
}

// ---------------------------------------------------------------------------
// Kernel 2: out[b,i,h] = Ux[b,i,h] + (sum_j gate*Vx[b,j,h]) / (1e-20 + sum_j gate)
// Persistent/balanced: gridDim.x = #SMs, 512 threads, 1 CTA/SM (160KB smem).
// Each CTA takes a contiguous slice of the 2048 rows (<=2 batch crossings,
// so <=2 Vx stagings). Gate streamed once via float4 __ldcs. Double-buffered
// SMEM partials so 15/16 warps keep streaming across the per-row reduction.
// ---------------------------------------------------------------------------
__global__ void agg_kernel(const float* __restrict__ gate, float* __restrict__ out) {
    extern __shared__ float smraw[];
    float4* sVx  = (float4*)smraw;        // 8192 float4  (Vx[b]: 256 x 128 f32)
    float4* sAgg = sVx + 8192;            // 2 x 16 x 32
    float4* sDen = sAgg + 1024;           // 2 x 16 x 32

    const int tid = threadIdx.x;

    // balanced contiguous row slice for this CTA
    const int G   = gridDim.x;
    const int rb  = (int)(((long long)blockIdx.x       * ROWS) / G);
    const int re  = (int)(((long long)(blockIdx.x + 1) * ROWS) / G);

    const int h4 = tid & 31;              // float4 column 0..31  (h = 4*h4..)
    const int jl = tid >> 5;              // j-lane 0..15
    const float4* Ux4  = (const float4*)g_Ux;
    float4*       out4 = (float4*)out;

    int cur_b = -1;
    int it = 0;
    for (int row = rb; row < re; ++row, ++it) {
        const int b = row >> 8;           // row / NSEQ
        if (b != cur_b) {
            __syncthreads();              // all prior sVx reads / reductions done
            const float4* Vx4 = ((const float4*)g_Vx) + b * 8192;
            for (int idx = tid; idx < 8192; idx += 512) sVx[idx] = Vx4[idx];
            __syncthreads();
            cur_b = b;
        }

        const float4* grow = ((const float4*)gate) + (size_t)row * 8192 + jl * 512 + h4;

        float4 agg = make_float4(0.f, 0.f, 0.f, 0.f);
        float4 den = make_float4(0.f, 0.f, 0.f, 0.f);
#pragma unroll 4
        for (int jj = 0; jj < 16; jj++) {
            float4 g = __ldcs(grow + jj * 32);
            float4 v = sVx[(jl * 16 + jj) * 32 + h4];
            agg.x += g.x * v.x; agg.y += g.y * v.y;
            agg.z += g.z * v.z; agg.w += g.w * v.w;
            den.x += g.x; den.y += g.y; den.z += g.z; den.w += g.w;
        }

        float4* bufA = sAgg + (it & 1) * 512;
        float4* bufD = sDen + (it & 1) * 512;
        bufA[jl * 32 + h4] = agg;
        bufD[jl * 32 + h4] = den;
        __syncthreads();

        if (tid < 32) {   // warp 0 reduces + writes while others stream next row
            float4 a = make_float4(0.f, 0.f, 0.f, 0.f);
            float4 d = make_float4(0.f, 0.f, 0.f, 0.f);
#pragma unroll
            for (int w = 0; w < 16; w++) {
                float4 pa = bufA[w * 32 + tid];
                float4 pd = bufD[w * 32 + tid];
                a.x += pa.x; a.y += pa.y; a.z += pa.z; a.w += pa.w;
                d.x += pd.x; d.y += pd.y; d.z += pd.z; d.w += pd.w;
            }
            float4 u = Ux4[row * 32 + tid];
            float4 o;
            o.x = u.x + a.x / (1e-20f + d.x);
            o.y = u.y + a.y / (1e-20f + d.y);
            o.z = u.z + a.z / (1e-20f + d.z);
            o.w = u.w + a.w / (1e-20f + d.w);
            out4[row * 32 + tid] = o;
        }
    }
}

// ---------------------------------------------------------------------------
extern "C" void kernel_launch(void* const* d_in, const int* in_sizes, int n_in,
                              void* d_out, int out_size) {
    const float *x = nullptr, *gate = nullptr;
    const float *Uw = nullptr, *Ub = nullptr, *Vw = nullptr, *Vb = nullptr;

    // select inputs by element count (robust to PN/NN scalar placement)
    for (int i = 0; i < n_in; i++) {
        int s = in_sizes[i];
        if (s == 262144 && !x)            x    = (const float*)d_in[i];
        else if (s == 67108864 && !gate)  gate = (const float*)d_in[i];
        else if (s == 16384) { if (!Uw) Uw = (const float*)d_in[i];
                               else if (!Vw) Vw = (const float*)d_in[i]; }
        else if (s == 128)   { if (!Ub) Ub = (const float*)d_in[i];
                               else if (!Vb) Vb = (const float*)d_in[i]; }
    }

    int nsm = 148;
    cudaDeviceGetAttribute(&nsm, cudaDevAttrMultiProcessorCount, 0);  // capture-time only
    if (nsm < 1 || nsm > 1024) nsm = 148;

    const size_t sm1 = (size_t)(2 * 128 * 129 + 8 * 128) * sizeof(float);  // 136192 B
    const size_t sm2 = (size_t)(8192 + 1024 + 1024) * sizeof(float4);      // 163840 B
    cudaFuncSetAttribute(uv_kernel,  cudaFuncAttributeMaxDynamicSharedMemorySize, (int)sm1);
    cudaFuncSetAttribute(agg_kernel, cudaFuncAttributeMaxDynamicSharedMemorySize, (int)sm2);

    uv_kernel<<<256, 256, sm1>>>(x, Uw, Ub, Vw, Vb);
    agg_kernel<<<nsm, 512, sm2>>>(gate, (float*)d_out);
}

// round 3
// speedup vs baseline: 1.0521x; 1.0521x over previous
#include <cuda_runtime.h>

#define HH   128
#define NSEQ 256
#define BB   8
#define ROWS (BB * NSEQ)   // 2048

// scratch (allocation-free rule: __device__ globals)
__device__ float g_Ux[ROWS * HH];
__device__ float g_Vx[ROWS * HH];

// ---------------------------------------------------------------------------
// Kernel 1: Ux = (x @ U_w^T + U_b)*0.5 ; Vx = (x @ V_w^T + V_b)*0.5
// 128 blocks x 512 threads, 16 rows/block -> single wave on 152 SMs.
// W transposed into padded SMEM (129 stride). Thread groups: (mat, row-half).
// ---------------------------------------------------------------------------
__global__ void uv_kernel(const float* __restrict__ x,
                          const float* __restrict__ Uw, const float* __restrict__ Ub,
                          const float* __restrict__ Vw, const float* __restrict__ Vb) {
    extern __shared__ float sm[];
    float* sWu = sm;                    // 128*129
    float* sWv = sm + 128 * 129;        // 128*129
    float* sx  = sm + 2 * 128 * 129;    // 16*128
    const int tid = threadIdx.x;

    // load W transposed via float4 gmem reads: sW[h*129 + k] = W[k*128 + h]
    for (int idx = tid; idx < 128 * 32; idx += 512) {
        const int k  = idx >> 5;
        const int h  = (idx & 31) * 4;
        float4 u = ((const float4*)Uw)[idx];
        float4 v = ((const float4*)Vw)[idx];
        sWu[(h + 0) * 129 + k] = u.x; sWu[(h + 1) * 129 + k] = u.y;
        sWu[(h + 2) * 129 + k] = u.z; sWu[(h + 3) * 129 + k] = u.w;
        sWv[(h + 0) * 129 + k] = v.x; sWv[(h + 1) * 129 + k] = v.y;
        sWv[(h + 2) * 129 + k] = v.z; sWv[(h + 3) * 129 + k] = v.w;
    }
    const int r0 = blockIdx.x * 16;
    for (int idx = tid; idx < 16 * HH; idx += 512)
        sx[idx] = x[r0 * HH + idx];
    __syncthreads();

    const int grp = tid >> 7;          // 0..3
    const int k   = tid & 127;
    const int mat = grp & 1;           // 0 = U, 1 = V
    const int rh  = (grp >> 1) * 8;    // row half: 0 or 8
    const float* W = mat ? sWv : sWu;

    float acc[8];
#pragma unroll
    for (int r = 0; r < 8; r++) acc[r] = 0.0f;

#pragma unroll 8
    for (int h = 0; h < HH; h++) {
        float wv = W[h * 129 + k];
#pragma unroll
        for (int r = 0; r < 8; r++) acc[r] += sx[(rh + r) * HH + h] * wv;
    }

    const float bias = mat ? Vb[k] : Ub[k];
    float* dst = mat ? g_Vx : g_Ux;
#pragma unroll
    for (int r = 0; r < 8; r++)
        dst[(r0 + rh + r) * HH + k] = (acc[r] + bias) * 0.5f;
}

// ---------------------------------------------------------------------------
// Kernel 2: out[b,i,h] = Ux[b,i,h] + (sum_j gate*Vx[b,j,h]) / (1e-20 + sum_j gate)
// Persistent: grid = #SMs, 512 threads, 1 CTA/SM (128KB smem = Vx[b]).
// WARP-PER-ROW: each warp owns a full output row (32 lanes x float4 = H=128),
// streams the row's 128KB of gate with fully independent unroll-8 __ldcs
// loads, accumulates agg+den in registers, writes out directly.
// No cross-warp reduction, no per-row barriers (only Vx staging syncs).
// ---------------------------------------------------------------------------
__global__ void agg_kernel(const float* __restrict__ gate, float* __restrict__ out) {
    extern __shared__ float4 sVx[];       // 8192 float4 = Vx[b]: 256 x 32
    const int tid  = threadIdx.x;
    const int lane = tid & 31;            // h4: float4 column 0..31
    const int wrp  = tid >> 5;            // 0..15

    const int G  = gridDim.x;
    const int rb = (int)(((long long)blockIdx.x       * ROWS) / G);
    const int re = (int)(((long long)(blockIdx.x + 1) * ROWS) / G);

    const float4* gate4 = (const float4*)gate;
    const float4* Ux4   = (const float4*)g_Ux;
    float4*       out4  = (float4*)out;

    int segb = rb;
    while (segb < re) {
        const int b    = segb >> 8;                     // batch of this segment
        const int sege = min(re, (b + 1) << 8);

        __syncthreads();                                // prior sVx reads done
        const float4* Vx4 = ((const float4*)g_Vx) + b * 8192;
        for (int idx = tid; idx < 8192; idx += 512) sVx[idx] = Vx4[idx];
        __syncthreads();

        for (int row = segb + wrp; row < sege; row += 16) {
            const float4* grow = gate4 + (size_t)row * 8192 + lane;

            float4 agg = make_float4(0.f, 0.f, 0.f, 0.f);
            float4 den = make_float4(0.f, 0.f, 0.f, 0.f);
#pragma unroll 8
            for (int j = 0; j < 256; j++) {
                float4 g = __ldcs(grow + j * 32);
                float4 v = sVx[j * 32 + lane];
                agg.x += g.x * v.x; agg.y += g.y * v.y;
                agg.z += g.z * v.z; agg.w += g.w * v.w;
                den.x += g.x; den.y += g.y; den.z += g.z; den.w += g.w;
            }

            float4 u = Ux4[(size_t)row * 32 + lane];
            float4 o;
            o.x = u.x + agg.x / (1e-20f + den.x);
            o.y = u.y + agg.y / (1e-20f + den.y);
            o.z = u.z + agg.z / (1e-20f + den.z);
            o.w = u.w + agg.w / (1e-20f + den.w);
            out4[(size_t)row * 32 + lane] = o;
        }
        segb = sege;
    }
}

// ---------------------------------------------------------------------------
extern "C" void kernel_launch(void* const* d_in, const int* in_sizes, int n_in,
                              void* d_out, int out_size) {
    const float *x = nullptr, *gate = nullptr;
    const float *Uw = nullptr, *Ub = nullptr, *Vw = nullptr, *Vb = nullptr;

    // select inputs by element count (robust to PN/NN scalar placement)
    for (int i = 0; i < n_in; i++) {
        int s = in_sizes[i];
        if (s == 262144 && !x)            x    = (const float*)d_in[i];
        else if (s == 67108864 && !gate)  gate = (const float*)d_in[i];
        else if (s == 16384) { if (!Uw) Uw = (const float*)d_in[i];
                               else if (!Vw) Vw = (const float*)d_in[i]; }
        else if (s == 128)   { if (!Ub) Ub = (const float*)d_in[i];
                               else if (!Vb) Vb = (const float*)d_in[i]; }
    }

    int nsm = 152;
    cudaDeviceGetAttribute(&nsm, cudaDevAttrMultiProcessorCount, 0);  // capture-time only
    if (nsm < 1 || nsm > 1024) nsm = 152;

    const size_t sm1 = (size_t)(2 * 128 * 129 + 16 * 128) * sizeof(float); // 140288 B
    const size_t sm2 = (size_t)8192 * sizeof(float4);                      // 131072 B
    cudaFuncSetAttribute(uv_kernel,  cudaFuncAttributeMaxDynamicSharedMemorySize, (int)sm1);
    cudaFuncSetAttribute(agg_kernel, cudaFuncAttributeMaxDynamicSharedMemorySize, (int)sm2);

    uv_kernel<<<128, 512, sm1>>>(x, Uw, Ub, Vw, Vb);
    agg_kernel<<<nsm, 512, sm2>>>(gate, (float*)d_out);
}

// round 10
// speedup vs baseline: 1.5908x; 1.5120x over previous
#include <cuda_runtime.h>

#define HH   128
#define NSEQ 256
#define BB   8
#define ROWS (BB * NSEQ)   // 2048

// scratch (allocation-free rule: __device__ globals)
__device__ float g_Ux[ROWS * HH];
__device__ float g_Vx[ROWS * HH];

// ---------------------------------------------------------------------------
// Kernel 1: Ux = (x @ U_w^T + U_b)*0.5 ; Vx = (x @ V_w^T + V_b)*0.5
// 128 blocks x 512 threads, 16 rows/block -> single wave.
// All-float4 SMEM: W rows stored untransposed, padded to 33 float4/row so
// lane-strided LDS.128 is conflict-free. x rows read as float4 broadcasts.
// ---------------------------------------------------------------------------
__global__ void __launch_bounds__(512, 1)
uv_kernel(const float* __restrict__ x,
          const float* __restrict__ Uw, const float* __restrict__ Ub,
          const float* __restrict__ Vw, const float* __restrict__ Vb) {
    extern __shared__ float4 sm4[];
    float4* sWu = sm4;                   // 128 rows x 33 float4 (pad)
    float4* sWv = sm4 + 128 * 33;        // 128 rows x 33 float4
    float4* sx4 = sm4 + 2 * 128 * 33;    // 16 rows x 32 float4
    const int tid = threadIdx.x;

    // stage W (row k contiguous, no transpose) and x, all float4
    for (int idx = tid; idx < 128 * 32; idx += 512) {
        const int k  = idx >> 5;
        const int h4 = idx & 31;
        sWu[k * 33 + h4] = ((const float4*)Uw)[idx];
        sWv[k * 33 + h4] = ((const float4*)Vw)[idx];
    }
    const int r0 = blockIdx.x * 16;
    for (int idx = tid; idx < 16 * 32; idx += 512)
        sx4[idx] = ((const float4*)x)[r0 * 32 + idx];
    __syncthreads();

    const int grp = tid >> 7;          // 0..3
    const int k   = tid & 127;
    const int mat = grp & 1;           // 0 = U, 1 = V
    const int rh  = (grp >> 1) * 8;    // row half: 0 or 8
    const float4* W = (mat ? sWv : sWu) + k * 33;

    float acc[8];
#pragma unroll
    for (int r = 0; r < 8; r++) acc[r] = 0.0f;

#pragma unroll 4
    for (int h4 = 0; h4 < 32; h4++) {
        const float4 w = W[h4];
#pragma unroll
        for (int r = 0; r < 8; r++) {
            const float4 xv = sx4[(rh + r) * 32 + h4];   // broadcast across lanes
            acc[r] += xv.x * w.x + xv.y * w.y + xv.z * w.z + xv.w * w.w;
        }
    }

    const float bias = mat ? Vb[k] : Ub[k];
    float* dst = mat ? g_Vx : g_Ux;
#pragma unroll
    for (int r = 0; r < 8; r++)
        dst[(r0 + rh + r) * HH + k] = (acc[r] + bias) * 0.5f;
}

// ---------------------------------------------------------------------------
// Kernel 2: out[b,i,h] = Ux[b,i,h] + (sum_j gate*Vx[b,j,h]) / (1e-20 + sum_j gate)
// Persistent: grid = #SMs, 512 threads, 1 CTA/SM (128KB smem = Vx[b]).
// WARP-PER-ROW with EXPLICIT double-buffered register pipeline: prefetch the
// next batch of 8 independent LDG.128 before consuming the current batch.
// __launch_bounds__(512,1) allows ~128 regs/thread so buf[2][8] (64 regs)
// stays in registers — forcing ~8 loads in flight per thread (64KB/SM).
// ---------------------------------------------------------------------------
__global__ void __launch_bounds__(512, 1)
agg_kernel(const float* __restrict__ gate, float* __restrict__ out) {
    extern __shared__ float4 sVx[];       // 8192 float4 = Vx[b]: 256 x 32
    const int tid  = threadIdx.x;
    const int lane = tid & 31;            // float4 column 0..31
    const int wrp  = tid >> 5;            // 0..15

    const int G  = gridDim.x;
    const int rb = (int)(((long long)blockIdx.x       * ROWS) / G);
    const int re = (int)(((long long)(blockIdx.x + 1) * ROWS) / G);

    const float4* gate4 = (const float4*)gate;
    const float4* Ux4   = (const float4*)g_Ux;
    float4*       out4  = (float4*)out;

    int segb = rb;
    while (segb < re) {
        const int b    = segb >> 8;                     // batch of this segment
        const int sege = min(re, (b + 1) << 8);

        __syncthreads();                                // prior sVx reads done
        const float4* Vx4 = ((const float4*)g_Vx) + b * 8192;
        for (int idx = tid; idx < 8192; idx += 512) sVx[idx] = Vx4[idx];
        __syncthreads();

        for (int row = segb + wrp; row < sege; row += 16) {
            const float4* grow = gate4 + (size_t)row * 8192 + lane;

            float4 buf[2][8];
            float4 agg = make_float4(0.f, 0.f, 0.f, 0.f);
            float4 den = make_float4(0.f, 0.f, 0.f, 0.f);

            // prologue: fill buffer 0
#pragma unroll
            for (int u = 0; u < 8; u++)
                buf[0][u] = __ldcs(grow + u * 32);

            // 32 batches of 8 j's; unroll 2 so (jb & 1) is compile-time
#pragma unroll 2
            for (int jb = 0; jb < 32; jb++) {
                const int cur = jb & 1;
                if (jb < 31) {
                    const float4* nx = grow + (jb + 1) * 8 * 32;
#pragma unroll
                    for (int u = 0; u < 8; u++)
                        buf[cur ^ 1][u] = __ldcs(nx + u * 32);
                }
#pragma unroll
                for (int u = 0; u < 8; u++) {
                    const float4 g = buf[cur][u];
                    const float4 v = sVx[(jb * 8 + u) * 32 + lane];
                    agg.x += g.x * v.x; agg.y += g.y * v.y;
                    agg.z += g.z * v.z; agg.w += g.w * v.w;
                    den.x += g.x; den.y += g.y; den.z += g.z; den.w += g.w;
                }
            }

            const float4 u4 = Ux4[(size_t)row * 32 + lane];
            float4 o;
            o.x = u4.x + agg.x / (1e-20f + den.x);
            o.y = u4.y + agg.y / (1e-20f + den.y);
            o.z = u4.z + agg.z / (1e-20f + den.z);
            o.w = u4.w + agg.w / (1e-20f + den.w);
            out4[(size_t)row * 32 + lane] = o;
        }
        segb = sege;
    }
}

// ---------------------------------------------------------------------------
extern "C" void kernel_launch(void* const* d_in, const int* in_sizes, int n_in,
                              void* d_out, int out_size) {
    const float *x = nullptr, *gate = nullptr;
    const float *Uw = nullptr, *Ub = nullptr, *Vw = nullptr, *Vb = nullptr;

    // select inputs by element count (robust to PN/NN scalar placement)
    for (int i = 0; i < n_in; i++) {
        int s = in_sizes[i];
        if (s == 262144 && !x)            x    = (const float*)d_in[i];
        else if (s == 67108864 && !gate)  gate = (const float*)d_in[i];
        else if (s == 16384) { if (!Uw) Uw = (const float*)d_in[i];
                               else if (!Vw) Vw = (const float*)d_in[i]; }
        else if (s == 128)   { if (!Ub) Ub = (const float*)d_in[i];
                               else if (!Vb) Vb = (const float*)d_in[i]; }
    }

    int nsm = 152;
    cudaDeviceGetAttribute(&nsm, cudaDevAttrMultiProcessorCount, 0);  // capture-time only
    if (nsm < 1 || nsm > 1024) nsm = 152;

    const size_t sm1 = (size_t)(2 * 128 * 33 + 16 * 32) * sizeof(float4);  // 143360 B
    const size_t sm2 = (size_t)8192 * sizeof(float4);                      // 131072 B
    cudaFuncSetAttribute(uv_kernel,  cudaFuncAttributeMaxDynamicSharedMemorySize, (int)sm1);
    cudaFuncSetAttribute(agg_kernel, cudaFuncAttributeMaxDynamicSharedMemorySize, (int)sm2);

    uv_kernel<<<128, 512, sm1>>>(x, Uw, Ub, Vw, Vb);
    agg_kernel<<<nsm, 512, sm2>>>(gate, (float*)d_out);
}